// round 2
// baseline (speedup 1.0000x reference)
#include <cuda_runtime.h>

#define NN 1024
#define DD 128
#define HH 64
#define BB 2

// Scratch (device globals: no allocation allowed in kernel_launch)
__device__ float g_AI[BB * NN * HH];              // [bn][h]
__device__ float g_AJ[BB * (HH / 2) * NN * 2];    // [b][hp][n][2]  (h-pair-major, packed)

// ---------------------------------------------------------------------------
// Kernel A: projections.  AI[bn][h] = emb[bn]·Wi[h],  AJ[b][hp][n] = emb·Wj + b1
// 128 blocks x 256 threads; each block handles 16 rows; W1 slice cached in regs.
// ---------------------------------------------------------------------------
__global__ __launch_bounds__(256) void proj_kernel(const float* __restrict__ emb,
                                                   const float* __restrict__ W1,
                                                   const float* __restrict__ b1)
{
    __shared__ float emb_s[16 * 128];
    const int tid = threadIdx.x;
    const int bn0 = blockIdx.x * 16;

    {
        const float4* src = (const float4*)(emb + (size_t)bn0 * DD);
        float4* dst = (float4*)emb_s;
        for (int idx = tid; idx < 16 * 128 / 4; idx += 256) dst[idx] = src[idx];
    }

    const int warp = tid >> 5, lane = tid & 31;
    const int o = warp * 16 + (lane & 15);   // output index 0..127
    const int dhalf = lane >> 4;             // split the 128-d dot across 2 half-warps
    const int part = o >> 6;                 // 0 -> AI (Wi), 1 -> AJ (Wj)
    const int h = o & 63;

    float4 w1r[16];
    const float4* wsrc = (const float4*)(W1 + h * (2 * DD) + part * DD + dhalf * 64);
#pragma unroll
    for (int i = 0; i < 16; i++) w1r[i] = wsrc[i];

    __syncthreads();

    const float b1v = b1[h];
    for (int nl = 0; nl < 16; nl++) {
        const float4* er = (const float4*)(emb_s + nl * 128 + dhalf * 64);
        float a0 = 0.f, a1 = 0.f, a2 = 0.f, a3 = 0.f;
#pragma unroll
        for (int i = 0; i < 16; i++) {
            float4 e = er[i], w = w1r[i];
            a0 = fmaf(e.x, w.x, a0);
            a1 = fmaf(e.y, w.y, a1);
            a2 = fmaf(e.z, w.z, a2);
            a3 = fmaf(e.w, w.w, a3);
        }
        float acc = (a0 + a1) + (a2 + a3);
        acc += __shfl_xor_sync(0xffffffffu, acc, 16);
        if (dhalf == 0) {
            const int bn = bn0 + nl;
            if (part == 0) {
                g_AI[bn * HH + h] = acc;
            } else {
                const int b = bn >> 10, n = bn & (NN - 1);
                g_AJ[(((b * (HH / 2)) + (h >> 1)) * NN + n) * 2 + (h & 1)] = acc + b1v;
            }
        }
    }
}

// ---------------------------------------------------------------------------
// Kernel B: edge weights.  Packed f32x2 inner loop: per 2 h:
//   add.rn.f32x2 (fma pipe) + 2x max.f32 (alu pipe) + fma.rn.f32x2 (fma pipe)
// CTA = 16 rows x 512 j.  Thread = 4 rows x 8 j (each aj load serves 4 edges).
// ---------------------------------------------------------------------------
__device__ __forceinline__ void edge_step(unsigned long long& acc,
                                          unsigned long long ai,
                                          unsigned long long aj,
                                          unsigned long long w)
{
    asm("{\n\t"
        ".reg .f32 lo, hi;\n\t"
        ".reg .b64 t;\n\t"
        "add.rn.f32x2 t, %1, %2;\n\t"
        "mov.b64 {lo, hi}, t;\n\t"
        "max.f32 lo, lo, 0f00000000;\n\t"
        "max.f32 hi, hi, 0f00000000;\n\t"
        "mov.b64 t, {lo, hi};\n\t"
        "fma.rn.f32x2 %0, t, %3, %0;\n\t"
        "}\n"
        : "+l"(acc) : "l"(ai), "l"(aj), "l"(w));
}

#define ROWS 16
#define JT 512
#define EDGE_SMEM (32 * JT * 8 + ROWS * HH * 4 + HH * 4)   // 135424 B

extern __shared__ unsigned char smem_raw[];

__global__ __launch_bounds__(256, 1) void edge_kernel(const int* __restrict__ visited,
                                                      const float* __restrict__ W2,
                                                      const float* __restrict__ b2,
                                                      float* __restrict__ out)
{
    unsigned long long* AJ_s = (unsigned long long*)smem_raw;         // [32][512] h-pairs
    float* AI_s = (float*)(smem_raw + 32 * JT * 8);                   // [16][64]
    float* w2_s = AI_s + ROWS * HH;                                   // [64]

    const int tid = threadIdx.x;
    const int bi = blockIdx.x;
    const int jhalf = bi & 1;
    const int rt = bi >> 1;            // 0..127 row tiles
    const int b = rt >> 6;
    const int i0 = (rt & 63) * ROWS;
    const int j0 = jhalf * JT;

    // Stage aj' tile [32 hp][512 j] into smem (contiguous per hp row in gmem).
    {
        float4* dst = (float4*)AJ_s;
        for (int idx = tid; idx < 32 * JT / 2; idx += 256) {
            const int hp = idx >> 8;
            const int jj = (idx & 255) << 1;
            dst[idx] = *(const float4*)(g_AJ +
                (size_t)(((b * (HH / 2) + hp) * NN) + j0 + jj) * 2);
        }
    }
    {
        const float4* src = (const float4*)(g_AI + (size_t)(b * NN + i0) * HH);
        ((float4*)AI_s)[tid] = src[tid];   // 16*64/4 = 256 float4
    }
    if (tid < HH) w2_s[tid] = W2[tid];
    __syncthreads();

    const int g = tid >> 6;        // row group 0..3 (warp-uniform)
    const int lg = tid & 63;       // j lane
    const int rbase = g * 4;

    unsigned long long acc[4][8];
#pragma unroll
    for (int r = 0; r < 4; r++)
#pragma unroll
        for (int k = 0; k < 8; k++) acc[r][k] = 0ull;

#pragma unroll 1
    for (int hc = 0; hc < 4; hc++) {   // 4 chunks of 16 h (8 pairs)
        unsigned long long AIc[4][8], w2c[8];
#pragma unroll
        for (int p = 0; p < 8; p++)
            w2c[p] = *(const unsigned long long*)&w2_s[hc * 16 + 2 * p];
#pragma unroll
        for (int r = 0; r < 4; r++)
#pragma unroll
            for (int p = 0; p < 8; p++)
                AIc[r][p] = *(const unsigned long long*)&AI_s[(rbase + r) * HH + hc * 16 + 2 * p];

#pragma unroll
        for (int k = 0; k < 8; k++) {
            const int j = lg + (k << 6);
            unsigned long long aj[8];
#pragma unroll
            for (int p = 0; p < 8; p++)
                aj[p] = AJ_s[(hc * 8 + p) * JT + j];
#pragma unroll
            for (int p = 0; p < 8; p++)
#pragma unroll
                for (int r = 0; r < 4; r++)
                    edge_step(acc[r][k], AIc[r][p], aj[p], w2c[p]);
        }
    }

    const float b2v = b2[0];
    int vrow[4];
#pragma unroll
    for (int r = 0; r < 4; r++) vrow[r] = visited[b * NN + i0 + rbase + r];

#pragma unroll
    for (int k = 0; k < 8; k++) {
        const int j = j0 + lg + (k << 6);
        const int vc = visited[b * NN + j];
#pragma unroll
        for (int r = 0; r < 4; r++) {
            float lo, hi;
            asm("mov.b64 {%0, %1}, %2;" : "=f"(lo), "=f"(hi) : "l"(acc[r][k]));
            const float s = lo + hi + b2v;
            const bool m = (vrow[r] | vc) != 0;
            out[(size_t)(b * NN + i0 + rbase + r) * NN + j] = m ? -1e9f : s;
        }
    }
}

// ---------------------------------------------------------------------------
// Kernel C: in-place row softmax.  One block per row, 256 threads x float4.
// ---------------------------------------------------------------------------
__global__ __launch_bounds__(256) void softmax_kernel(float* __restrict__ out)
{
    __shared__ float red[8];
    const int tid = threadIdx.x;
    float4* rp = (float4*)(out + (size_t)blockIdx.x * NN);
    float4 v = rp[tid];

    float m = fmaxf(fmaxf(v.x, v.y), fmaxf(v.z, v.w));
#pragma unroll
    for (int s = 16; s > 0; s >>= 1) m = fmaxf(m, __shfl_xor_sync(0xffffffffu, m, s));
    const int warp = tid >> 5, lane = tid & 31;
    if (lane == 0) red[warp] = m;
    __syncthreads();
    if (tid == 0) {
        float t = red[0];
#pragma unroll
        for (int i = 1; i < 8; i++) t = fmaxf(t, red[i]);
        red[0] = t;
    }
    __syncthreads();
    m = red[0];
    __syncthreads();

    float4 e;
    e.x = __expf(v.x - m); e.y = __expf(v.y - m);
    e.z = __expf(v.z - m); e.w = __expf(v.w - m);
    float s4 = (e.x + e.y) + (e.z + e.w);
#pragma unroll
    for (int s = 16; s > 0; s >>= 1) s4 += __shfl_xor_sync(0xffffffffu, s4, s);
    if (lane == 0) red[warp] = s4;
    __syncthreads();
    if (tid == 0) {
        float t = 0.f;
#pragma unroll
        for (int i = 0; i < 8; i++) t += red[i];
        red[0] = t;
    }
    __syncthreads();
    const float inv = 1.0f / red[0];
    e.x *= inv; e.y *= inv; e.z *= inv; e.w *= inv;
    rp[tid] = e;
}

// ---------------------------------------------------------------------------
extern "C" void kernel_launch(void* const* d_in, const int* in_sizes, int n_in,
                              void* d_out, int out_size)
{
    const float* emb = (const float*)d_in[0];
    const int* visited = (const int*)d_in[1];
    // d_in[2] = remaining_capacity: unused by the reference
    const float* W1 = (const float*)d_in[3];
    const float* b1 = (const float*)d_in[4];
    const float* W2 = (const float*)d_in[5];
    const float* b2 = (const float*)d_in[6];
    float* out = (float*)d_out;

    proj_kernel<<<128, 256>>>(emb, W1, b1);

    cudaFuncSetAttribute((const void*)edge_kernel,
                         cudaFuncAttributeMaxDynamicSharedMemorySize, EDGE_SMEM);
    edge_kernel<<<256, 256, EDGE_SMEM>>>(visited, W2, b2, out);

    softmax_kernel<<<BB * NN, 256>>>(out);
}

// round 5
// speedup vs baseline: 1.0130x; 1.0130x over previous
#include <cuda_runtime.h>
#include <cstdint>

#define NN 1024
#define DD 128
#define HH 64
#define BB 2

// Scratch (device globals: no allocation allowed in kernel_launch)
__device__ float g_AI[BB * NN * HH];              // [bn][h]
__device__ float g_AJ[BB * (HH / 2) * NN * 2];    // [b][hp][n][2]  (h-pair-major, packed)

// ---------------------------------------------------------------------------
// Kernel A: projections.  AI[bn][h] = emb[bn]·Wi[h],  AJ[b][hp][n] = emb·Wj + b1
// 512 blocks x 256 threads; each block handles 4 rows; W1 slice cached in regs.
// ---------------------------------------------------------------------------
__global__ __launch_bounds__(256) void proj_kernel(const float* __restrict__ emb,
                                                   const float* __restrict__ W1,
                                                   const float* __restrict__ b1)
{
    __shared__ float emb_s[4 * 128];
    const int tid = threadIdx.x;
    const int bn0 = blockIdx.x * 4;

    if (tid < 4 * 128 / 4) {
        const float4* src = (const float4*)(emb + (size_t)bn0 * DD);
        ((float4*)emb_s)[tid] = src[tid];
    }

    const int warp = tid >> 5, lane = tid & 31;
    const int o = warp * 16 + (lane & 15);   // output index 0..127
    const int dhalf = lane >> 4;             // split the 128-d dot across 2 half-warps
    const int part = o >> 6;                 // 0 -> AI (Wi), 1 -> AJ (Wj)
    const int h = o & 63;

    float4 w1r[16];
    const float4* wsrc = (const float4*)(W1 + h * (2 * DD) + part * DD + dhalf * 64);
#pragma unroll
    for (int i = 0; i < 16; i++) w1r[i] = wsrc[i];

    __syncthreads();

    const float b1v = b1[h];
#pragma unroll
    for (int nl = 0; nl < 4; nl++) {
        const float4* er = (const float4*)(emb_s + nl * 128 + dhalf * 64);
        float a0 = 0.f, a1 = 0.f, a2 = 0.f, a3 = 0.f;
#pragma unroll
        for (int i = 0; i < 16; i++) {
            float4 e = er[i], w = w1r[i];
            a0 = fmaf(e.x, w.x, a0);
            a1 = fmaf(e.y, w.y, a1);
            a2 = fmaf(e.z, w.z, a2);
            a3 = fmaf(e.w, w.w, a3);
        }
        float acc = (a0 + a1) + (a2 + a3);
        acc += __shfl_xor_sync(0xffffffffu, acc, 16);
        if (dhalf == 0) {
            const int bn = bn0 + nl;
            if (part == 0) {
                g_AI[bn * HH + h] = acc;
            } else {
                const int b = bn >> 10, n = bn & (NN - 1);
                g_AJ[(((b * (HH / 2)) + (h >> 1)) * NN + n) * 2 + (h & 1)] = acc + b1v;
            }
        }
    }
}

// ---------------------------------------------------------------------------
// Kernel B (fused): edge weights + mask + row softmax.
// Block = 16 rows x 1024 j (full rows), 512 threads, thread = 4 rows x 8 j.
// AJ staged in 4 x 64KB h-chunks (synchronous LDG->STS, single buffer).
// Packed f32x2 inner op: FADD2 (fma) + 2x FMNMX (alu) + FFMA2 (fma).
// ---------------------------------------------------------------------------
__device__ __forceinline__ void edge_step(unsigned long long& acc,
                                          unsigned long long ai,
                                          unsigned long long aj,
                                          unsigned long long w)
{
    asm("{\n\t"
        ".reg .f32 lo, hi;\n\t"
        ".reg .b64 t;\n\t"
        "add.rn.f32x2 t, %1, %2;\n\t"
        "mov.b64 {lo, hi}, t;\n\t"
        "max.f32 lo, lo, 0f00000000;\n\t"
        "max.f32 hi, hi, 0f00000000;\n\t"
        "mov.b64 t, {lo, hi};\n\t"
        "fma.rn.f32x2 %0, t, %3, %0;\n\t"
        "}\n"
        : "+l"(acc) : "l"(ai), "l"(aj), "l"(w));
}

#define ROWS 16
#define JT 1024
#define HC 4                 // h-pair chunks
#define HPC 8                // h-pairs per chunk
#define CHUNK_BYTES (HPC * JT * 8)          // 65536
// smem: buf | AI (16*64*4) | w2 (256) | redM (256) | redS (256)
#define OFF_AI   (CHUNK_BYTES)
#define OFF_W2   (OFF_AI + ROWS * HH * 4)
#define OFF_RM   (OFF_W2 + 256)
#define OFF_RS   (OFF_RM + 256)
#define EDGE_SMEM (OFF_RS + 256)

extern __shared__ unsigned char smem_raw[];

__global__ __launch_bounds__(512, 1) void edge_kernel(const int* __restrict__ visited,
                                                      const float* __restrict__ W2,
                                                      const float* __restrict__ b2,
                                                      float* __restrict__ out)
{
    float* AI_s = (float*)(smem_raw + OFF_AI);
    float* w2_s = (float*)(smem_raw + OFF_W2);
    float* redM = (float*)(smem_raw + OFF_RM);
    float* redS = (float*)(smem_raw + OFF_RS);

    const int tid = threadIdx.x;
    const int bi = blockIdx.x;
    const int b = bi >> 6;
    const int i0 = (bi & 63) * ROWS;

    // Stage AI tile + w2
    if (tid < ROWS * HH / 4) {
        const float4* src = (const float4*)(g_AI + (size_t)(b * NN + i0) * HH);
        ((float4*)AI_s)[tid] = src[tid];
    }
    if (tid < HH) w2_s[tid] = W2[tid];

    const int g = tid >> 7;        // row group 0..3
    const int lg = tid & 127;      // j lane 0..127
    const int w = (tid >> 5) & 3;  // warp within group
    const int rbase = g * 4;

    int vrow[4], vcol[8];
#pragma unroll
    for (int r = 0; r < 4; r++) vrow[r] = visited[b * NN + i0 + rbase + r];
#pragma unroll
    for (int k = 0; k < 8; k++) vcol[k] = visited[b * NN + lg + (k << 7)];
    const float b2v = b2[0];

    unsigned long long acc[4][8];
#pragma unroll
    for (int r = 0; r < 4; r++)
#pragma unroll
        for (int k = 0; k < 8; k++) acc[r][k] = 0ull;

#pragma unroll 1
    for (int hc = 0; hc < HC; hc++) {
        __syncthreads();   // protect buf from previous iteration's readers
        // Stage chunk hc: [HPC hp][JT j] h-pairs, contiguous in gmem.
        {
            const float4* src = (const float4*)(g_AJ
                + (size_t)b * (HH / 2) * NN * 2
                + (size_t)hc * HPC * NN * 2);
            float4* dst = (float4*)smem_raw;
#pragma unroll
            for (int it = 0; it < CHUNK_BYTES / 16 / 512; it++)
                dst[tid + it * 512] = src[tid + it * 512];
        }
        __syncthreads();

        const unsigned long long* buf = (const unsigned long long*)smem_raw;

#pragma unroll
        for (int p = 0; p < HPC; p++) {
            const unsigned long long w2p =
                *(const unsigned long long*)&w2_s[hc * 16 + 2 * p];
            unsigned long long aiv[4];
#pragma unroll
            for (int r = 0; r < 4; r++)
                aiv[r] = *(const unsigned long long*)&AI_s[(rbase + r) * HH + hc * 16 + 2 * p];
            unsigned long long aj[8];
#pragma unroll
            for (int k = 0; k < 8; k++)
                aj[k] = buf[p * JT + lg + (k << 7)];
#pragma unroll
            for (int k = 0; k < 8; k++)
#pragma unroll
                for (int r = 0; r < 4; r++)
                    edge_step(acc[r][k], aiv[r], aj[k], w2p);
        }
    }

    // ---- epilogue: unpack, mask, softmax over each full row, write out ----
    float v[4][8];
#pragma unroll
    for (int r = 0; r < 4; r++)
#pragma unroll
        for (int k = 0; k < 8; k++) {
            float lo, hi;
            asm("mov.b64 {%0, %1}, %2;" : "=f"(lo), "=f"(hi) : "l"(acc[r][k]));
            const float s = lo + hi + b2v;
            v[r][k] = ((vrow[r] | vcol[k]) != 0) ? -1e9f : s;
        }

    // row max: thread-local -> warp -> 4 warps via smem
    float mloc[4];
#pragma unroll
    for (int r = 0; r < 4; r++) {
        float m = v[r][0];
#pragma unroll
        for (int k = 1; k < 8; k++) m = fmaxf(m, v[r][k]);
#pragma unroll
        for (int s = 16; s > 0; s >>= 1) m = fmaxf(m, __shfl_xor_sync(0xffffffffu, m, s));
        if ((tid & 31) == 0) redM[(g * 4 + r) * 4 + w] = m;
        mloc[r] = m;
    }
    __syncthreads();
#pragma unroll
    for (int r = 0; r < 4; r++) {
        const float* rm = &redM[(g * 4 + r) * 4];
        mloc[r] = fmaxf(fmaxf(rm[0], rm[1]), fmaxf(rm[2], rm[3]));
    }

    // exp + row sum
#pragma unroll
    for (int r = 0; r < 4; r++) {
        float s = 0.f;
#pragma unroll
        for (int k = 0; k < 8; k++) {
            v[r][k] = __expf(v[r][k] - mloc[r]);
            s += v[r][k];
        }
#pragma unroll
        for (int sh = 16; sh > 0; sh >>= 1) s += __shfl_xor_sync(0xffffffffu, s, sh);
        if ((tid & 31) == 0) redS[(g * 4 + r) * 4 + w] = s;
    }
    __syncthreads();
#pragma unroll
    for (int r = 0; r < 4; r++) {
        const float* rs = &redS[(g * 4 + r) * 4];
        const float inv = 1.0f / ((rs[0] + rs[1]) + (rs[2] + rs[3]));
        float* rowp = out + (size_t)(b * NN + i0 + rbase + r) * NN;
#pragma unroll
        for (int k = 0; k < 8; k++)
            rowp[lg + (k << 7)] = v[r][k] * inv;
    }
}

// ---------------------------------------------------------------------------
extern "C" void kernel_launch(void* const* d_in, const int* in_sizes, int n_in,
                              void* d_out, int out_size)
{
    const float* emb = (const float*)d_in[0];
    const int* visited = (const int*)d_in[1];
    // d_in[2] = remaining_capacity: unused by the reference
    const float* W1 = (const float*)d_in[3];
    const float* b1 = (const float*)d_in[4];
    const float* W2 = (const float*)d_in[5];
    const float* b2 = (const float*)d_in[6];
    float* out = (float*)d_out;

    proj_kernel<<<512, 256>>>(emb, W1, b1);

    cudaFuncSetAttribute((const void*)edge_kernel,
                         cudaFuncAttributeMaxDynamicSharedMemorySize, EDGE_SMEM);
    edge_kernel<<<128, 512, EDGE_SMEM>>>(visited, W2, b2, out);
}